// round 2
// baseline (speedup 1.0000x reference)
#include <cuda_runtime.h>
#include <math.h>
#include <stdint.h>

#define BB 8
#define NN 2500
#define EE 100
#define FF 50
#define YY 8922
#define KK 9
#define BY (BB*YY)

// attention tiling
#define TY   12
#define CN   192
#define HP   54
#define NPAD 2501
#define NCH  14        // ceil(2500/192)

typedef unsigned long long ull;

__device__ float g_h[BB*NN*FF];     // conv output h[b][n][f]
__device__ float g_loss[BY];        // per-(b,y) BCE terms

__device__ __forceinline__ void ffma2(ull &d, ull a, ull b) {
    asm("fma.rn.f32x2 %0, %1, %2, %0;" : "+l"(d) : "l"(a), "l"(b));
}
__device__ __forceinline__ ull pk2(float v) {
    ull r; unsigned u = __float_as_uint(v);
    asm("mov.b64 %0, {%1, %2};" : "=l"(r) : "r"(u), "r"(u));
    return r;
}
__device__ __forceinline__ float lo32(ull v){ return __uint_as_float((unsigned)v); }
__device__ __forceinline__ float hi32(ull v){ return __uint_as_float((unsigned)(v>>32)); }

__device__ __forceinline__ void cp_commit(){ asm volatile("cp.async.commit_group;"); }
template<int W> __device__ __forceinline__ void cp_wait(){ asm volatile("cp.async.wait_group %0;" :: "n"(W)); }

// ======================= Kernel 1: embed + conv1d(K=9,SAME) + tanh =======================
// grid (40, 8), 128 threads. thread = (nl in 0..31, eq in 0..3); n in {nl, nl+32}.
__global__ __launch_bounds__(128, 1)
void conv_kernel(const int* __restrict__ x, const float* __restrict__ embW,
                 const float* __restrict__ convW, const float* __restrict__ convB) {
    extern __shared__ float sm[];
    float* emb = sm;                   // 72*101 = 7272
    float* wsm = emb + 72*101;         // 900*50 = 45000, wsm[(e*9+k)*50+f]
    int*  toks = (int*)(wsm + 45000);  // 72

    int b = blockIdx.y, base = blockIdx.x * 64, tid = threadIdx.x;

    if (tid < 72) {
        int n = base - 4 + tid;
        toks[tid] = (n >= 0 && n < NN) ? x[b*NN + n] : -1;
    }
    __syncthreads();
    // W transposed: coalesced global reads (r contiguous for fixed f)
    for (int j = tid; j < FF*EE*KK; j += 128) {
        int f = j / 900, r = j - f*900;
        wsm[r*FF + f] = convW[j];
    }
    // embedding gather (pad 101 -> conflict-free scalar reads)
    for (int j = tid; j < 72*EE; j += 128) {
        int row = j / EE, c = j - row*EE;
        int tk = toks[row];
        emb[row*101 + c] = (tk >= 0) ? embW[(size_t)tk*EE + c] : 0.f;
    }
    __syncthreads();

    int nl = tid & 31;        // lane within warp -> conflict-free emb reads
    int eq = tid >> 5;        // e-quarter

    ull acc[2][25];
    #pragma unroll
    for (int j = 0; j < 2; j++)
        #pragma unroll
        for (int q = 0; q < 25; q++) acc[j][q] = 0ull;

    for (int ee = 0; ee < 25; ee++) {
        int e = eq*25 + ee;
        for (int k = 0; k < KK; k++) {
            ull v0 = pk2(emb[(nl + k)*101 + e]);
            ull v1 = pk2(emb[(nl + 32 + k)*101 + e]);
            const ull* wr = (const ull*)&wsm[(e*KK + k)*FF];
            #pragma unroll
            for (int q = 0; q < 25; q++) {
                ull w = wr[q];
                ffma2(acc[0][q], w, v0);
                ffma2(acc[1][q], w, v1);
            }
        }
    }
    __syncthreads();
    // partial reduction over e-quarters: alias scratch onto emb/wsm region
    float* part = sm;  // needs 3*64*50 = 9600 floats
    if (eq > 0) {
        #pragma unroll
        for (int j = 0; j < 2; j++) {
            int nloc = nl + 32*j;
            float* p = part + (eq-1)*3200 + nloc*FF;
            #pragma unroll
            for (int q = 0; q < 25; q++) {
                p[2*q]   = lo32(acc[j][q]);
                p[2*q+1] = hi32(acc[j][q]);
            }
        }
    }
    __syncthreads();
    if (eq == 0) {
        #pragma unroll
        for (int j = 0; j < 2; j++) {
            int nloc = nl + 32*j;
            int n = base + nloc;
            if (n >= NN) continue;
            float* dst = &g_h[((size_t)b*NN + n)*FF];
            #pragma unroll
            for (int q = 0; q < 25; q++) {
                float a0 = lo32(acc[j][q]) + part[nloc*FF+2*q]   + part[3200+nloc*FF+2*q]   + part[6400+nloc*FF+2*q]   + convB[2*q];
                float a1 = hi32(acc[j][q]) + part[nloc*FF+2*q+1] + part[3200+nloc*FF+2*q+1] + part[6400+nloc*FF+2*q+1] + convB[2*q+1];
                dst[2*q]   = tanhf(a0);
                dst[2*q+1] = tanhf(a1);
            }
        }
    }
}

// ======================= Kernel 2: fused scores -> softmax -> alpha -> logits =======================
__device__ __forceinline__ void load_chunk(float* hs_buf, const float* hb, int c, int tid) {
    int n0 = c * CN;
    for (int idx = tid; idx < CN*25; idx += 256) {
        int n = idx / 25, f2 = idx - n*25;
        int gn = n0 + n;
        int ok = (gn < NN) ? 8 : 0;
        const float* src = hb + (size_t)(gn < NN ? gn : 0)*FF + 2*f2;
        uint32_t dst = (uint32_t)__cvta_generic_to_shared(&hs_buf[n*HP + 2*f2]);
        asm volatile("cp.async.ca.shared.global [%0], [%1], 8, %2;" :: "r"(dst), "l"(src), "r"(ok));
    }
}

__global__ __launch_bounds__(256, 1)
void attn_kernel(const float* __restrict__ Uw, const float* __restrict__ finW,
                 const float* __restrict__ finB, const float* __restrict__ tgt,
                 float* __restrict__ yhat_out, float* __restrict__ alpha_out) {
    extern __shared__ float sm[];
    float* s   = sm;                     // TY*NPAD = 30012
    float* hs  = s + TY*NPAD;            // 2*CN*HP = 20736
    float* Us  = hs + 2*CN*HP;           // 600
    float* Fs  = Us + TY*FF;             // 600
    float* red = Fs + TY*FF;             // 24

    int b = blockIdx.y;
    int y0 = blockIdx.x * TY;
    int tid = threadIdx.x;
    const float* hb = g_h + (size_t)b*NN*FF;

    // stage U/final rows
    for (int j = tid; j < TY*FF; j += 256) {
        int t = j / FF, f = j - t*FF;
        int y = y0 + t;
        Us[j] = (y < YY) ? Uw[(size_t)y*FF + f] : 0.f;
        Fs[j] = (y < YY) ? finW[(size_t)y*FF + f] : 0.f;
    }

    int tn = tid & 63, tt = tid >> 6;    // thread tile: n in {tn, tn+64, tn+128}, ty in {3tt..3tt+2}

    // ---------------- Phase A: scores ----------------
    load_chunk(hs, hb, 0, tid); cp_commit();
    for (int c = 0; c < NCH; c++) {
        if (c + 1 < NCH) { load_chunk(hs + ((c+1)&1)*CN*HP, hb, c+1, tid); cp_commit(); cp_wait<1>(); }
        else cp_wait<0>();
        __syncthreads();
        const float* hc = hs + (c&1)*CN*HP;
        ull a[3][3];
        #pragma unroll
        for (int r = 0; r < 3; r++)
            #pragma unroll
            for (int j = 0; j < 3; j++) a[r][j] = 0ull;
        #pragma unroll
        for (int fp = 0; fp < 25; fp++) {
            ull h0 = *(const ull*)&hc[tn*HP + 2*fp];
            ull h1 = *(const ull*)&hc[(tn+64)*HP + 2*fp];
            ull h2 = *(const ull*)&hc[(tn+128)*HP + 2*fp];
            ull u0 = *(const ull*)&Us[(tt*3+0)*FF + 2*fp];
            ull u1 = *(const ull*)&Us[(tt*3+1)*FF + 2*fp];
            ull u2 = *(const ull*)&Us[(tt*3+2)*FF + 2*fp];
            ffma2(a[0][0], u0, h0); ffma2(a[0][1], u0, h1); ffma2(a[0][2], u0, h2);
            ffma2(a[1][0], u1, h0); ffma2(a[1][1], u1, h1); ffma2(a[1][2], u1, h2);
            ffma2(a[2][0], u2, h0); ffma2(a[2][1], u2, h1); ffma2(a[2][2], u2, h2);
        }
        #pragma unroll
        for (int r = 0; r < 3; r++)
            #pragma unroll
            for (int j = 0; j < 3; j++) {
                int gn = c*CN + tn + 64*j;
                if (gn < NN) s[(tt*3+r)*NPAD + gn] = lo32(a[r][j]) + hi32(a[r][j]);
            }
        __syncthreads();
    }

    // prefetch chunk 0 for phase C while softmax runs
    load_chunk(hs, hb, 0, tid); cp_commit();

    // ---------------- Phase B: softmax + alpha write ----------------
    {
        int w = tid >> 5, lane = tid & 31;
        for (int yl = w; yl < TY; yl += 8) {
            float* sr = s + yl*NPAD;
            float m = -1e30f;
            for (int i = lane; i < NN; i += 32) m = fmaxf(m, sr[i]);
            #pragma unroll
            for (int o = 16; o; o >>= 1) m = fmaxf(m, __shfl_xor_sync(~0u, m, o));
            float d = 0.f;
            for (int i = lane; i < NN; i += 32) { float e = __expf(sr[i] - m); sr[i] = e; d += e; }
            #pragma unroll
            for (int o = 16; o; o >>= 1) d += __shfl_xor_sync(~0u, d, o);
            float inv = 1.f / d;
            int y = y0 + yl;
            bool valid = (y < YY);
            float* ao = alpha_out + ((size_t)b*YY + (valid ? y : 0))*NN;
            for (int i = lane; i < NN; i += 32) {
                float al = sr[i] * inv;
                sr[i] = al;
                if (valid) ao[i] = al;
            }
        }
    }
    __syncthreads();

    // ---------------- Phase C: logits = sum_n alpha * (h . final) ----------------
    float lg[3] = {0.f, 0.f, 0.f};
    for (int c = 0; c < NCH; c++) {
        if (c + 1 < NCH) { load_chunk(hs + ((c+1)&1)*CN*HP, hb, c+1, tid); cp_commit(); cp_wait<1>(); }
        else cp_wait<0>();
        __syncthreads();
        const float* hc = hs + (c&1)*CN*HP;
        ull a[3][3];
        #pragma unroll
        for (int r = 0; r < 3; r++)
            #pragma unroll
            for (int j = 0; j < 3; j++) a[r][j] = 0ull;
        #pragma unroll
        for (int fp = 0; fp < 25; fp++) {
            ull h0 = *(const ull*)&hc[tn*HP + 2*fp];
            ull h1 = *(const ull*)&hc[(tn+64)*HP + 2*fp];
            ull h2 = *(const ull*)&hc[(tn+128)*HP + 2*fp];
            ull u0 = *(const ull*)&Fs[(tt*3+0)*FF + 2*fp];
            ull u1 = *(const ull*)&Fs[(tt*3+1)*FF + 2*fp];
            ull u2 = *(const ull*)&Fs[(tt*3+2)*FF + 2*fp];
            ffma2(a[0][0], u0, h0); ffma2(a[0][1], u0, h1); ffma2(a[0][2], u0, h2);
            ffma2(a[1][0], u1, h0); ffma2(a[1][1], u1, h1); ffma2(a[1][2], u1, h2);
            ffma2(a[2][0], u2, h0); ffma2(a[2][1], u2, h1); ffma2(a[2][2], u2, h2);
        }
        #pragma unroll
        for (int r = 0; r < 3; r++)
            #pragma unroll
            for (int j = 0; j < 3; j++) {
                int gn = c*CN + tn + 64*j;
                if (gn < NN) lg[r] += s[(tt*3+r)*NPAD + gn] * (lo32(a[r][j]) + hi32(a[r][j]));
            }
        __syncthreads();
    }

    // reduce lg over the 64 tn-threads (2 warps per tt)
    #pragma unroll
    for (int r = 0; r < 3; r++) {
        float v = lg[r];
        #pragma unroll
        for (int o = 16; o; o >>= 1) v += __shfl_xor_sync(~0u, v, o);
        if ((tid & 31) == 0) red[(tid >> 5)*3 + r] = v;
    }
    __syncthreads();

    if (tid < TY) {
        int tq = tid / 3, r = tid - tq*3;
        float v = red[(2*tq)*3 + r] + red[(2*tq+1)*3 + r];
        int y = y0 + tid;
        if (y < YY) {
            float logit = v + finB[y];
            float p = 1.f / (1.f + __expf(-logit));
            yhat_out[(size_t)b*YY + y] = p;
            float pc = fminf(fmaxf(p, 1e-7f), 1.f - 1e-7f);
            float t = tgt[(size_t)b*YY + y];
            g_loss[(size_t)b*YY + y] = -(t*logf(pc) + (1.f - t)*log1pf(-pc));
        }
    }
}

// ======================= Kernel 3: deterministic loss reduction =======================
__global__ void loss_kernel(float* __restrict__ out) {
    __shared__ float r[256];
    int tid = threadIdx.x;
    float a = 0.f;
    for (int i = tid; i < BY; i += 256) a += g_loss[i];
    r[tid] = a;
    __syncthreads();
    for (int st = 128; st > 0; st >>= 1) {
        if (tid < st) r[tid] += r[tid + st];
        __syncthreads();
    }
    if (tid == 0) out[BY] = r[0] / (float)BY;
}

// ======================= Launch =======================
extern "C" void kernel_launch(void* const* d_in, const int* in_sizes, int n_in,
                              void* d_out, int out_size) {
    const int*   x      = (const int*)d_in[0];
    const float* target = (const float*)d_in[1];
    const float* embW   = (const float*)d_in[2];
    const float* convW  = (const float*)d_in[3];
    const float* convB  = (const float*)d_in[4];
    const float* Uw     = (const float*)d_in[5];
    const float* finW   = (const float*)d_in[6];
    const float* finB   = (const float*)d_in[7];
    float* out = (float*)d_out;
    float* yhat  = out;            // [B,Y]
    float* alpha = out + BY + 1;   // [B,Y,N]; out[BY] = loss

    const int conv_smem = (72*101 + 45000)*4 + 72*4;            // 209376
    const int attn_smem = (TY*NPAD + 2*CN*HP + 2*TY*FF + 32)*4; // 207920

    cudaFuncSetAttribute(conv_kernel, cudaFuncAttributeMaxDynamicSharedMemorySize, conv_smem);
    cudaFuncSetAttribute(attn_kernel, cudaFuncAttributeMaxDynamicSharedMemorySize, attn_smem);

    conv_kernel<<<dim3((NN + 63)/64, BB), 128, conv_smem>>>(x, embW, convW, convB);
    attn_kernel<<<dim3((YY + TY - 1)/TY, BB), 256, attn_smem>>>(Uw, finW, finB, target, yhat, alpha);
    loss_kernel<<<1, 256>>>(out);
}